// round 10
// baseline (speedup 1.0000x reference)
#include <cuda_runtime.h>
#include <math_constants.h>

#define NB 8
#define NPTS 4096
#define KNN 16
#define MPTS (NB * NPTS)
#define CH 32
#define NCLS 40
#define GR 32                   // grid resolution per axis
#define G3 (GR * GR * GR)
#define GMIN (-5.5f)
#define CW (11.0f / 32.0f)      // 0.34375, exact in fp32
#define INVCW (32.0f / 11.0f)

__device__ int    g_cnt[NB * G3];
__device__ int    g_start[NB * G3];
__device__ int    g_cur[NB * G3];
__device__ int    g_pcell[MPTS];
__device__ float4 g_spt[MPTS];       // grid-sorted points (x,y,z,|p|^2)
__device__ int    g_soi[MPTS];       // sorted slot -> original global index
__device__ int    g_knn[MPTS * KNN];
__device__ float  g_y[MPTS * CH];
__device__ float4 g_feat[MPTS * 17];
__device__ float  g_pool[NB * CH];

__device__ __forceinline__ int cellco(float v) {
    int c = (int)floorf((v - GMIN) * INVCW);
    return min(GR - 1, max(0, c));
}

__device__ __forceinline__ float safe_norm3(float x, float y, float z) {
    float s = x * x + y * y + z * z;
    return s > 0.f ? sqrtf(s) : 0.f;
}

__device__ __forceinline__ float angle3(float ax, float ay, float az,
                                        float bx, float by, float bz) {
    float cx = ay * bz - az * by;
    float cy = az * bx - ax * bz;
    float cz = ax * by - ay * bx;
    float cn = safe_norm3(cx, cy, cz);
    float d  = ax * bx + ay * by + az * bz;
    bool ok = (cn > 0.f) || (d != 0.f);
    return ok ? atan2f(cn, d) : 0.f;
}

// ---------------------------------------------------------------------------
// grid build
// ---------------------------------------------------------------------------
__global__ __launch_bounds__(256) void zero_kernel() {
    int i = blockIdx.x * 256 + threadIdx.x;
    if (i < NB * G3) g_cnt[i] = 0;
    if (i < NB * CH) g_pool[i] = 0.f;
}

__global__ __launch_bounds__(256) void count_kernel(const float* __restrict__ pos) {
    int i = blockIdx.x * 256 + threadIdx.x;
    int b = i >> 12;
    int cx = cellco(pos[3 * i + 0]);
    int cy = cellco(pos[3 * i + 1]);
    int cz = cellco(pos[3 * i + 2]);
    int cid = ((b * GR + cz) * GR + cy) * GR + cx;
    g_pcell[i] = cid;
    atomicAdd(&g_cnt[cid], 1);
}

// per-batch exclusive scan of 32768 cell counts (one block per batch)
__global__ __launch_bounds__(1024) void scan_kernel() {
    __shared__ int buf[1024];
    int b = blockIdx.x, t = threadIdx.x;
    int run = 0;
    for (int c = 0; c < G3 / 1024; c++) {
        int idx = b * G3 + c * 1024 + t;
        int v = g_cnt[idx];
        buf[t] = v;
        __syncthreads();
        for (int off = 1; off < 1024; off <<= 1) {
            int x = buf[t];
            if (t >= off) x += buf[t - off];
            __syncthreads();
            buf[t] = x;
            __syncthreads();
        }
        int excl = buf[t] - v;
        g_start[idx] = run + excl;
        g_cur[idx]   = run + excl;
        run += buf[1023];
        __syncthreads();
    }
}

__global__ __launch_bounds__(256) void scatter_kernel(const float* __restrict__ pos) {
    int i = blockIdx.x * 256 + threadIdx.x;
    int b = i >> 12;
    int cid = g_pcell[i];
    int slot = atomicAdd(&g_cur[cid], 1);       // per-batch offset 0..4095
    float x = pos[3 * i + 0], y = pos[3 * i + 1], z = pos[3 * i + 2];
    g_spt[b * NPTS + slot] = make_float4(x, y, z, x * x + y * y + z * z);
    g_soi[b * NPTS + slot] = i;
}

// ---------------------------------------------------------------------------
// kNN v6: exact grid ring search. One warp per query; lane = cell within the
// current Chebyshev shell, serially iterating its cell's points. Selection
// machinery identical to the proven warp-select (slots in lanes 0..15).
// Terminate when real 16th-best d2 <= ((r-1)*CW)^2 (safety factor 0.999).
// ---------------------------------------------------------------------------
__global__ __launch_bounds__(256) void knn_kernel(const float* __restrict__ pos) {
    const unsigned FULL = 0xFFFFFFFFu;
    const float INF = CUDART_INF_F;
    int lane = threadIdx.x & 31;
    int warp = threadIdx.x >> 5;
    int q    = blockIdx.x * 8 + warp;
    int batch = q >> 12;
    int boff  = batch * NPTS;

    float qx = pos[3 * q + 0], qy = pos[3 * q + 1], qz = pos[3 * q + 2];
    float m2x = -2.f * qx, m2y = -2.f * qy, m2z = -2.f * qz;
    float qw = qx * qx + qy * qy + qz * qz;
    int cx = cellco(qx), cy = cellco(qy), cz = cellco(qz);

    float L  = INF;           // sorted top-16 in lanes 0..15 (shifted d2)
    int   LI = boff;
    float tp = INF;           // 16th best (shifted)

    for (int r = 1; r < GR; r++) {
        if (r >= 2) {         // can shell r contain anything better?
            float rd = (float)(r - 1) * CW;
            if (tp + qw <= rd * rd * 0.999f) break;
        }
        int side = 2 * r + 1, side2 = side * side, tot = side2 * side;
        for (int baseI = 0; baseI < tot; baseI += 32) {
            int idx = baseI + lane;
            int cnt = 0, ptr = 0;
            if (idx < tot) {
                int dz = idx / side2, rem = idx - dz * side2;
                int dy = rem / side,  dx  = rem - dy * side;
                dx -= r; dy -= r; dz -= r;
                int m = max(abs(dx), max(abs(dy), abs(dz)));
                int ax = cx + dx, ay = cy + dy, az = cz + dz;
                bool shell = (r == 1) ? true : (m == r);  // r==1: cube incl. center
                if (shell && ax >= 0 && ax < GR && ay >= 0 && ay < GR &&
                    az >= 0 && az < GR) {
                    int cid = ((batch * GR + az) * GR + ay) * GR + ax;
                    cnt = g_cnt[cid];
                    ptr = g_start[cid];
                }
            }
            while (__any_sync(FULL, cnt > 0)) {
                float d = INF;
                int   oi = -1;
                if (cnt > 0) {
                    float4 c = g_spt[boff + ptr];
                    oi = g_soi[boff + ptr];
                    d = fmaf(c.x, m2x, fmaf(c.y, m2y, fmaf(c.z, m2z, c.w)));
                    if (oi == q) d = INF;         // exclude self
                    ptr++; cnt--;
                }
                unsigned bal = __ballot_sync(FULL, d < tp);
                while (bal) {
                    int src = __ffs(bal) - 1;
                    float v = __shfl_sync(FULL, d, src);
                    int  vi = __shfl_sync(FULL, oi, src);
                    unsigned ble = __ballot_sync(FULL, L <= v);
                    int pos_ = __popc(ble & 0xFFFFu);
                    float Lup = __shfl_up_sync(FULL, L, 1);
                    int  LIup = __shfl_up_sync(FULL, LI, 1);
                    if (lane < 16) {
                        if (lane == pos_)      { L = v;   LI = vi;   }
                        else if (lane > pos_)  { L = Lup; LI = LIup; }
                    }
                    tp = __shfl_sync(FULL, L, 15);
                    bal &= bal - 1;
                }
            }
        }
    }
    if (lane < 16) g_knn[q * KNN + lane] = LI;   // LI = original global index
}

// ---------------------------------------------------------------------------
// conv1 (+ fused y = w2a[0:32]^T x1 + b2a; materializes PPF feats)
// ---------------------------------------------------------------------------
__global__ __launch_bounds__(256) void conv1_kernel(
    const float* __restrict__ pos, const float* __restrict__ nrm,
    const float* __restrict__ w1a, const float* __restrict__ b1a,
    const float* __restrict__ w1b, const float* __restrict__ b1b,
    const float* __restrict__ w2a, const float* __restrict__ b2a)
{
    __shared__ float4 sf[8][20];
    __shared__ float  sh[8][17][32];
    int warp = threadIdx.x >> 5;
    int lane = threadIdx.x & 31;
    int i    = blockIdx.x * 8 + warp;

    float wa0 = w1a[0 * 32 + lane], wa1 = w1a[1 * 32 + lane];
    float wa2 = w1a[2 * 32 + lane], wa3 = w1a[3 * 32 + lane];
    float ba  = b1a[lane];
    float wb[32];
#pragma unroll
    for (int k = 0; k < 32; k++) wb[k] = w1b[k * 32 + lane];
    float bb = b1b[lane];

    float pix = pos[3 * i + 0], piy = pos[3 * i + 1], piz = pos[3 * i + 2];
    float nix = nrm[3 * i + 0], niy = nrm[3 * i + 1], niz = nrm[3 * i + 2];

    int j = (lane < KNN) ? g_knn[i * KNN + lane] : i;   // lane16 = self loop
    float pjx = pos[3 * j + 0], pjy = pos[3 * j + 1], pjz = pos[3 * j + 2];
    float njx = nrm[3 * j + 0], njy = nrm[3 * j + 1], njz = nrm[3 * j + 2];

    float px = pjx - pix, py = pjy - piy, pz = pjz - piz;
    float f0 = safe_norm3(px, py, pz);
    float f1 = angle3(nix, niy, niz, px, py, pz);
    float f2 = angle3(njx, njy, njz, px, py, pz);
    float f3 = angle3(nix, niy, niz, njx, njy, njz);
    if (lane < 17) {
        float4 f = make_float4(f0, f1, f2, f3);
        sf[warp][lane] = f;
        g_feat[i * 17 + lane] = f;
    }
    __syncwarp();

    for (int e = 0; e < 17; e++) {
        float4 f = sf[warp][e];
        float h = ba;
        h = fmaf(f.x, wa0, h); h = fmaf(f.y, wa1, h);
        h = fmaf(f.z, wa2, h); h = fmaf(f.w, wa3, h);
        sh[warp][e][lane] = fmaxf(h, 0.f);
    }
    __syncwarp();

    float best = -CUDART_INF_F;
    for (int e = 0; e < 17; e++) {
        float o0 = bb, o1 = 0.f, o2 = 0.f, o3 = 0.f;
        const float4* hv4 = (const float4*)sh[warp][e];
#pragma unroll
        for (int m = 0; m < 8; m++) {
            float4 hv = hv4[m];
            o0 = fmaf(hv.x, wb[4 * m + 0], o0);
            o1 = fmaf(hv.y, wb[4 * m + 1], o1);
            o2 = fmaf(hv.z, wb[4 * m + 2], o2);
            o3 = fmaf(hv.w, wb[4 * m + 3], o3);
        }
        best = fmaxf(best, (o0 + o1) + (o2 + o3));
    }
    float x1v = fmaxf(best, 0.f);

    sh[warp][0][lane] = x1v;
    __syncwarp();
    float w2[32];
#pragma unroll
    for (int k = 0; k < 32; k++) w2[k] = w2a[k * 32 + lane];
    float a0 = b2a[lane], a1 = 0.f, a2 = 0.f, a3 = 0.f;
    const float4* xv4 = (const float4*)sh[warp][0];
#pragma unroll
    for (int m = 0; m < 8; m++) {
        float4 xv = xv4[m];
        a0 = fmaf(xv.x, w2[4 * m + 0], a0);
        a1 = fmaf(xv.y, w2[4 * m + 1], a1);
        a2 = fmaf(xv.z, w2[4 * m + 2], a2);
        a3 = fmaf(xv.w, w2[4 * m + 3], a3);
    }
    g_y[i * CH + lane] = (a0 + a1) + (a2 + a3);
}

// ---------------------------------------------------------------------------
// conv2 (+ fused global max pool)
// ---------------------------------------------------------------------------
__global__ __launch_bounds__(256) void conv2_kernel(
    const float* __restrict__ w2a,
    const float* __restrict__ w2b, const float* __restrict__ b2b)
{
    __shared__ int   si[8][20];
    __shared__ float sh[8][17][32];
    __shared__ float red[8][32];
    int warp = threadIdx.x >> 5;
    int lane = threadIdx.x & 31;
    int i    = blockIdx.x * 8 + warp;

    float wa32 = w2a[32 * 32 + lane], wa33 = w2a[33 * 32 + lane];
    float wa34 = w2a[34 * 32 + lane], wa35 = w2a[35 * 32 + lane];
    float wb[32];
#pragma unroll
    for (int k = 0; k < 32; k++) wb[k] = w2b[k * 32 + lane];
    float bb = b2b[lane];

    int j = (lane < KNN) ? g_knn[i * KNN + lane] : i;
    if (lane < 17) si[warp][lane] = j;
    __syncwarp();

    float yv[17];
#pragma unroll
    for (int e = 0; e < 17; e++)
        yv[e] = g_y[si[warp][e] * CH + lane];

#pragma unroll
    for (int e = 0; e < 17; e++) {
        float4 f = g_feat[i * 17 + e];
        float h = yv[e];
        h = fmaf(f.x, wa32, h); h = fmaf(f.y, wa33, h);
        h = fmaf(f.z, wa34, h); h = fmaf(f.w, wa35, h);
        sh[warp][e][lane] = fmaxf(h, 0.f);
    }
    __syncwarp();

    float best = -CUDART_INF_F;
    for (int e = 0; e < 17; e++) {
        float o0 = bb, o1 = 0.f, o2 = 0.f, o3 = 0.f;
        const float4* hv4 = (const float4*)sh[warp][e];
#pragma unroll
        for (int m = 0; m < 8; m++) {
            float4 hv = hv4[m];
            o0 = fmaf(hv.x, wb[4 * m + 0], o0);
            o1 = fmaf(hv.y, wb[4 * m + 1], o1);
            o2 = fmaf(hv.z, wb[4 * m + 2], o2);
            o3 = fmaf(hv.w, wb[4 * m + 3], o3);
        }
        best = fmaxf(best, (o0 + o1) + (o2 + o3));
    }
    red[warp][lane] = fmaxf(best, 0.f);
    __syncthreads();

    if (warp == 0) {
        float m = red[0][lane];
#pragma unroll
        for (int r = 1; r < 8; r++) m = fmaxf(m, red[r][lane]);
        int b = (blockIdx.x * 8) >> 12;
        atomicMax((int*)&g_pool[b * CH + lane], __float_as_int(m));
    }
}

__global__ void fc_kernel(const float* __restrict__ wc,
                          const float* __restrict__ bc,
                          float* __restrict__ out) {
    int t = threadIdx.x;
    if (t < NB * NCLS) {
        int b = t / NCLS, o = t % NCLS;
        float acc = bc[o];
#pragma unroll
        for (int c = 0; c < CH; c++)
            acc = fmaf(g_pool[b * CH + c], wc[c * NCLS + o], acc);
        out[t] = acc;
    }
}

extern "C" void kernel_launch(void* const* d_in, const int* in_sizes, int n_in,
                              void* d_out, int out_size) {
    const float* pos = (const float*)d_in[0];
    const float* nrm = (const float*)d_in[1];
    const float* w1a = (const float*)d_in[3];
    const float* b1a = (const float*)d_in[4];
    const float* w1b = (const float*)d_in[5];
    const float* b1b = (const float*)d_in[6];
    const float* w2a = (const float*)d_in[7];
    const float* b2a = (const float*)d_in[8];
    const float* w2b = (const float*)d_in[9];
    const float* b2b = (const float*)d_in[10];
    const float* wc  = (const float*)d_in[11];
    const float* bc  = (const float*)d_in[12];
    float* out = (float*)d_out;

    zero_kernel<<<(NB * G3) / 256, 256>>>();
    count_kernel<<<MPTS / 256, 256>>>(pos);
    scan_kernel<<<NB, 1024>>>();
    scatter_kernel<<<MPTS / 256, 256>>>(pos);
    knn_kernel<<<MPTS / 8, 256>>>(pos);
    conv1_kernel<<<MPTS / 8, 256>>>(pos, nrm, w1a, b1a, w1b, b1b, w2a, b2a);
    conv2_kernel<<<MPTS / 8, 256>>>(w2a, w2b, b2b);
    fc_kernel<<<1, 320>>>(wc, bc, out);
}